// round 16
// baseline (speedup 1.0000x reference)
#include <cuda_runtime.h>
#include <cuda_fp16.h>
#include <stdint.h>
#include <float.h>

// Problem constants
#define D      256
#define KCODES 4096
#define NROWS  16384

#define THREADS 512
#define BM 128
#define BN 256
#define STAGES_PER_TILE 8
#define NT (KCODES / BN)
#define TOTAL_STAGES (STAGES_PER_TILE * NT)  // 128

#define A_STAGE_BYTES (BM * 64)
#define B_STAGE_BYTES (BN * 64)
#define STAGE_BYTES   (A_STAGE_BYTES + B_STAGE_BYTES)
#define SMEM_TOTAL    (2 * STAGE_BYTES)   // 49152

#define EMA_DECAY 0.99f
#define ONE_MINUS_DECAY 0.01f
#define EPS 1e-5f
#define GAP_T 0.03f

// rescan geometry: 16 k-chunks x 256 codes, 16 rows per group
#define RG_ROWS 16
#define RS_KC   16
#define RS_GRPS 64
#define RS_GRID (RS_KC * RS_GRPS)     // 1024

// prep grid: cb jobs FIRST, then init (zero g_dw + scratch), then z pack
#define P_CB_BLOCKS   (KCODES / 32)   // 128
#define P_INIT_BLOCKS 4096            // K*D floats / 256
#define P_Z_BLOCKS    8192
#define P_GRID (P_CB_BLOCKS + P_INIT_BLOCKS + P_Z_BLOCKS)

#define FIXUP_GRID 256
#define MERGE_GRID (KCODES * D / 4 / 256)   // 1024

// ---------------- device scratch ----------------
__device__ float g_cnorm[KCODES];
__device__ float g_n[KCODES];
__device__ int   g_idx[NROWS];
__device__ int   g_flag[NROWS];
__device__ int   g_list[NROWS];
__device__ int   g_cnt;
__device__ float g_scal[2];
__device__ unsigned long long g_best[NROWS];
__device__ float g_cbT[(size_t)D * KCODES];
__device__ float4 g_dw4[(size_t)KCODES * D / 4];   // 16B-aligned dw accumulator
__device__ __half2 g_za[(size_t)NROWS * 128];
__device__ __half2 g_cbp[(size_t)KCODES * 128];

// ---------------- helpers ----------------
__device__ __forceinline__ uint32_t smem_u32(const void* p) {
    uint32_t a;
    asm("{ .reg .u64 t; cvta.to.shared.u64 t, %1; cvt.u32.u64 %0, t; }" : "=r"(a) : "l"(p));
    return a;
}
__device__ __forceinline__ void cpasync16(uint32_t dst, const void* src) {
    asm volatile("cp.async.cg.shared.global [%0], [%1], 16;" :: "r"(dst), "l"(src));
}
__device__ __forceinline__ void cp_commit() {
    asm volatile("cp.async.commit_group;" ::: "memory");
}
__device__ __forceinline__ void cp_wait1() {
    asm volatile("cp.async.wait_group 1;" ::: "memory");
}
__device__ __forceinline__ void cp_wait0() {
    asm volatile("cp.async.wait_group 0;" ::: "memory");
}
__device__ __forceinline__ void mma_f16(float* c, uint32_t a0, uint32_t a1,
                                        uint32_t a2, uint32_t a3,
                                        uint32_t b0, uint32_t b1) {
    asm volatile(
        "mma.sync.aligned.m16n8k16.row.col.f32.f16.f16.f32 "
        "{%0,%1,%2,%3}, {%4,%5,%6,%7}, {%8,%9}, {%0,%1,%2,%3};"
        : "+f"(c[0]), "+f"(c[1]), "+f"(c[2]), "+f"(c[3])
        : "r"(a0), "r"(a1), "r"(a2), "r"(a3), "r"(b0), "r"(b1));
}
__device__ __forceinline__ void red_add_v4(float* p, float a, float b, float c, float d) {
    asm volatile("red.global.add.v4.f32 [%0], {%1,%2,%3,%4};"
                 :: "l"(p), "f"(a), "f"(b), "f"(c), "f"(d) : "memory");
}
__device__ __forceinline__ unsigned long long pack_sk(float s, int k) {
    uint32_t b = __float_as_uint(s);
    b = (b & 0x80000000u) ? ~b : (b | 0x80000000u);
    return ((unsigned long long)b << 32) | (unsigned long long)(0xFFFFFFFFu - (uint32_t)k);
}
__device__ __forceinline__ int perm_d(int chunk, int ws16) {
    int p0 = ws16 * 2;
    int q = p0 >> 3, j = p0 & 7;
    int kl = 2 * q + ((j >> 1) << 3) + (j & 1);
    return chunk * 32 + kl;
}

// ---------------- kernel 1: fused prep ----------------
__global__ __launch_bounds__(256) void vq_prep_kernel(
    const float* __restrict__ z, const float* __restrict__ cb)
{
    const int b = blockIdx.x;
    const int tid = threadIdx.x;

    if (b < P_CB_BLOCKS) {
        __shared__ float s[32][257];
        const int k0 = b * 32;
        for (int i = tid; i < 32 * 256; i += 256)
            s[i >> 8][i & 255] = cb[(size_t)(k0 + (i >> 8)) * D + (i & 255)];
        __syncthreads();

        const int wid = tid >> 5, lane = tid & 31;
        #pragma unroll
        for (int rr = 0; rr < 4; ++rr) {
            int r = wid * 4 + rr;
            float sum = 0.f;
            #pragma unroll
            for (int j = 0; j < 8; ++j) { float v = s[r][lane + 32 * j]; sum += v * v; }
            #pragma unroll
            for (int off = 16; off > 0; off >>= 1)
                sum += __shfl_down_sync(0xffffffffu, sum, off);
            if (lane == 0) g_cnorm[k0 + r] = 0.5f * sum;
        }
        for (int i = tid; i < 32 * 256; i += 256) {
            int d = i >> 5, j = i & 31;
            g_cbT[(size_t)d * KCODES + k0 + j] = s[j][d];
        }
        for (int i = tid; i < 32 * 128; i += 256) {
            int row = i >> 7, wi = i & 127;
            int d = perm_d(wi >> 4, wi & 15);
            g_cbp[(size_t)(k0 + row) * 128 + wi] =
                __halves2half2(__float2half_rn(s[row][d]), __float2half_rn(s[row][d + 1]));
        }
        return;
    }
    if (b < P_CB_BLOCKS + P_INIT_BLOCKS) {
        int i = (b - P_CB_BLOCKS) * 256 + tid;     // covers K*D floats
        reinterpret_cast<float*>(g_dw4)[i] = 0.0f;
        if (i < KCODES) g_n[i] = 0.0f;
        if (i < NROWS) g_best[i] = 0ull;
        if (i < 2) g_scal[i] = 0.0f;
        if (i == 0) g_cnt = 0;
        return;
    }
    {
        int w   = (b - P_CB_BLOCKS - P_INIT_BLOCKS) * 256 + tid;
        int row = w >> 7;
        int wi  = w & 127;
        int d   = perm_d(wi >> 4, wi & 15);
        float x0 = z[(size_t)row * D + d];
        float x1 = z[(size_t)row * D + d + 1];
        g_za[w] = __halves2half2(__float2half_rn(x0), __float2half_rn(x1));
    }
}

// ---------------- kernel 2: fp16 1-term GEMM + top-2 argmax + compact ----------
__global__ __launch_bounds__(THREADS, 1) void vq_mma_kernel()
{
    extern __shared__ char smem[];
    const uint32_t sbase = smem_u32(smem);
    const int tid  = threadIdx.x;
    const int wid  = tid >> 5;
    const int lane = tid & 31;
    const int r    = lane >> 2;
    const int q    = lane & 3;
    const int wm   = (wid >> 2) * 32;
    const int wn   = (wid & 3) * 64;
    const int mBase = blockIdx.x * BM;

    uint32_t aoff[2][2];
    #pragma unroll
    for (int mf = 0; mf < 2; ++mf)
        #pragma unroll
        for (int rr = 0; rr < 2; ++rr)
            aoff[mf][rr] = (uint32_t)(wm + mf * 16 + rr * 8 + r) * 64u + (uint32_t)q * 16u;
    uint32_t boff[8];
    #pragma unroll
    for (int nf = 0; nf < 8; ++nf)
        boff[nf] = (uint32_t)(wn + nf * 8 + r) * 64u + (uint32_t)q * 16u;

    float acc[2][8][4];
    float bestS[2][2], secS[2][2];
    int   bestI[2][2];
    #pragma unroll
    for (int mf = 0; mf < 2; ++mf)
        #pragma unroll
        for (int rr = 0; rr < 2; ++rr) {
            bestS[mf][rr] = -FLT_MAX; secS[mf][rr] = -FLT_MAX; bestI[mf][rr] = 0x7fffffff;
        }

    auto issue = [&](int s, int buf) {
        int nt = s >> 3;
        int kc = s & 7;
        const __half2* Asrc = g_za  + (size_t)mBase * 128 + kc * 16;
        const __half2* Bsrc = g_cbp + (size_t)(nt * BN) * 128 + kc * 16;
        uint32_t abase = sbase + (uint32_t)buf * STAGE_BYTES;
        uint32_t bbase = abase + A_STAGE_BYTES;
        {
            int i = tid;
            int row = i >> 2, c = i & 3;
            cpasync16(abase + (uint32_t)row * 64u + (uint32_t)c * 16u,
                      Asrc + (size_t)row * 128 + c * 4);
        }
        #pragma unroll
        for (int t = 0; t < 2; ++t) {
            int i = tid + t * THREADS;
            int row = i >> 2, c = i & 3;
            cpasync16(bbase + (uint32_t)row * 64u + (uint32_t)c * 16u,
                      Bsrc + (size_t)row * 128 + c * 4);
        }
        cp_commit();
    };

    issue(0, 0);

    for (int s = 0; s < TOTAL_STAGES; ++s) {
        const int buf = s & 1;
        if (s < TOTAL_STAGES - 1) { issue(s + 1, buf ^ 1); cp_wait1(); }
        else                       { cp_wait0(); }
        __syncthreads();

        int nt = s >> 3;
        int ks = s & 7;
        if (ks == 0) {
            #pragma unroll
            for (int mf = 0; mf < 2; ++mf)
                #pragma unroll
                for (int nf = 0; nf < 8; ++nf)
                    #pragma unroll
                    for (int e = 0; e < 4; ++e) acc[mf][nf][e] = 0.0f;
        }

        uint32_t abase = sbase + (uint32_t)buf * STAGE_BYTES;
        uint32_t bbase = abase + A_STAGE_BYTES;

        uint4 Af[2][2];
        #pragma unroll
        for (int mf = 0; mf < 2; ++mf)
            #pragma unroll
            for (int rr = 0; rr < 2; ++rr) {
                uint32_t addr = abase + aoff[mf][rr];
                asm volatile("ld.shared.v4.b32 {%0,%1,%2,%3}, [%4];"
                    : "=r"(Af[mf][rr].x), "=r"(Af[mf][rr].y),
                      "=r"(Af[mf][rr].z), "=r"(Af[mf][rr].w)
                    : "r"(addr));
            }
        #pragma unroll
        for (int nf = 0; nf < 8; ++nf) {
            uint4 Bf;
            uint32_t addr = bbase + boff[nf];
            asm volatile("ld.shared.v4.b32 {%0,%1,%2,%3}, [%4];"
                : "=r"(Bf.x), "=r"(Bf.y), "=r"(Bf.z), "=r"(Bf.w)
                : "r"(addr));
            #pragma unroll
            for (int mf = 0; mf < 2; ++mf) {
                mma_f16(acc[mf][nf],
                        Af[mf][0].x, Af[mf][1].x, Af[mf][0].y, Af[mf][1].y,
                        Bf.x, Bf.y);
                mma_f16(acc[mf][nf],
                        Af[mf][0].z, Af[mf][1].z, Af[mf][0].w, Af[mf][1].w,
                        Bf.z, Bf.w);
            }
        }

        if (ks == STAGES_PER_TILE - 1) {
            int ntBase = nt * BN;
            #pragma unroll
            for (int nf = 0; nf < 8; ++nf) {
                int colb = ntBase + wn + nf * 8 + q * 2;
                float cn0 = __ldg(&g_cnorm[colb]);
                float cn1 = __ldg(&g_cnorm[colb + 1]);
                #pragma unroll
                for (int mf = 0; mf < 2; ++mf) {
                    float sc[4];
                    sc[0] = acc[mf][nf][0] - cn0;
                    sc[1] = acc[mf][nf][1] - cn1;
                    sc[2] = acc[mf][nf][2] - cn0;
                    sc[3] = acc[mf][nf][3] - cn1;
                    #pragma unroll
                    for (int e = 0; e < 4; ++e) {
                        int rr = e >> 1;
                        int kk = colb + (e & 1);
                        float v = sc[e];
                        if (v > bestS[mf][rr]) {
                            secS[mf][rr] = bestS[mf][rr];
                            bestS[mf][rr] = v; bestI[mf][rr] = kk;
                        } else if (v > secS[mf][rr]) {
                            secS[mf][rr] = v;
                        }
                    }
                }
            }
        }
        __syncthreads();
    }

    float* redS  = reinterpret_cast<float*>(smem);
    int*   redI  = reinterpret_cast<int*>(smem + BM * 16 * 4);
    float* redS2 = reinterpret_cast<float*>(smem + BM * 16 * 8);
    int c16 = (wid & 3) * 4 + q;
    #pragma unroll
    for (int mf = 0; mf < 2; ++mf)
        #pragma unroll
        for (int rr = 0; rr < 2; ++rr) {
            int row = wm + mf * 16 + rr * 8 + r;
            redS [row * 16 + c16] = bestS[mf][rr];
            redI [row * 16 + c16] = bestI[mf][rr];
            redS2[row * 16 + c16] = secS[mf][rr];
        }
    __syncthreads();
    if (tid < BM) {
        float bs = redS[tid * 16];
        int   bi = redI[tid * 16];
        float ss = redS2[tid * 16];
        #pragma unroll
        for (int j = 1; j < 16; ++j) {
            float sv  = redS [tid * 16 + j];
            int   iv  = redI [tid * 16 + j];
            float s2v = redS2[tid * 16 + j];
            if (sv > bs || (sv == bs && iv < bi)) {
                ss = fmaxf(bs, s2v);
                bs = sv; bi = iv;
            } else {
                ss = fmaxf(ss, sv);
            }
        }
        int row = mBase + tid;
        int flag = (bs - ss < GAP_T) ? 1 : 0;
        g_idx[row]  = bi;
        g_flag[row] = flag;
        if (flag) {
            int p = atomicAdd(&g_cnt, 1);
            g_list[p] = row;
        }
    }
}

// ---------------- kernel 3 (s2): batched exact fp32 rescan (16 rows/group) ----
__global__ __launch_bounds__(256) void vq_rescan_kernel(const float* __restrict__ z)
{
    __shared__ float zs[RG_ROWS][256];
    __shared__ int   rows[RG_ROWS];
    __shared__ unsigned long long wbuf[RG_ROWS][8];

    const int tid  = threadIdx.x;
    const int lane = tid & 31;
    const int wid  = tid >> 5;
    const int k0   = (blockIdx.x & (RS_KC - 1)) * 256 + tid;
    const int nf   = g_cnt;
    const int ngrp = (nf + RG_ROWS - 1) / RG_ROWS;

    const float cn = g_cnorm[k0];

    for (int grp = blockIdx.x >> 4; grp < ngrp; grp += RS_GRPS) {
        __syncthreads();
        if (tid < RG_ROWS) {
            int i = grp * RG_ROWS + tid;
            rows[tid] = (i < nf) ? g_list[i] : -1;
        }
        __syncthreads();
        #pragma unroll
        for (int rr = 0; rr < RG_ROWS; ++rr) {
            int row = rows[rr];
            if (row >= 0) zs[rr][tid] = z[(size_t)row * D + tid];
        }
        __syncthreads();

        float acc[RG_ROWS];
        #pragma unroll
        for (int rr = 0; rr < RG_ROWS; ++rr) acc[rr] = 0.f;

        #pragma unroll 2
        for (int d4 = 0; d4 < D; d4 += 4) {
            float4 c;
            const float* p = g_cbT + (size_t)d4 * KCODES + k0;
            c.x = p[0];
            c.y = p[KCODES];
            c.z = p[2 * KCODES];
            c.w = p[3 * KCODES];
            #pragma unroll
            for (int rr = 0; rr < RG_ROWS; ++rr) {
                float4 zv = *reinterpret_cast<const float4*>(&zs[rr][d4]);
                acc[rr] += c.x * zv.x + c.y * zv.y + c.z * zv.z + c.w * zv.w;
            }
        }

        #pragma unroll
        for (int rr = 0; rr < RG_ROWS; ++rr) {
            unsigned long long pm = pack_sk(acc[rr] - cn, k0);
            #pragma unroll
            for (int off = 16; off > 0; off >>= 1) {
                unsigned long long qv = __shfl_xor_sync(0xffffffffu, pm, off);
                if (qv > pm) pm = qv;
            }
            if (lane == 0) wbuf[rr][wid] = pm;
        }
        __syncthreads();
        if (tid < RG_ROWS && rows[tid] >= 0) {
            unsigned long long pm = wbuf[tid][0];
            #pragma unroll
            for (int w = 1; w < 8; ++w)
                if (wbuf[tid][w] > pm) pm = wbuf[tid][w];
            atomicMax(&g_best[rows[tid]], pm);
        }
    }
}

// ---------------- kernel 4: gather for UNFLAGGED rows (v4 red into g_dw) -----
__global__ __launch_bounds__(256) void vq_gather_kernel(
    const float* __restrict__ z, const float* __restrict__ cb,
    const float* __restrict__ mask,
    float* __restrict__ out_q, float* __restrict__ out_idx)
{
    __shared__ float ws[8];
    __shared__ float msum;
    int tid = threadIdx.x;
    int l   = tid & 63;
    int row = blockIdx.x * 4 + (tid >> 6);
    int flag = g_flag[row];
    if (tid == 0) msum = 0.0f;
    __syncthreads();

    float s = 0.0f;
    if (!flag) {
        int idx = g_idx[row];
        float m = mask[row];
        float4 zv = reinterpret_cast<const float4*>(z  + (size_t)row * D)[l];
        float4 qv = reinterpret_cast<const float4*>(cb + (size_t)idx * D)[l];
        float4 o;
        o.x = zv.x + (qv.x - zv.x); o.y = zv.y + (qv.y - zv.y);
        o.z = zv.z + (qv.z - zv.z); o.w = zv.w + (qv.w - zv.w);
        reinterpret_cast<float4*>(out_q + (size_t)row * D)[l] = o;

        if (m != 0.0f) {
            red_add_v4(reinterpret_cast<float*>(g_dw4) + (size_t)idx * D + l * 4,
                       ONE_MINUS_DECAY * m * zv.x, ONE_MINUS_DECAY * m * zv.y,
                       ONE_MINUS_DECAY * m * zv.z, ONE_MINUS_DECAY * m * zv.w);
        }
        float dx = zv.x - qv.x, dy = zv.y - qv.y, dz = zv.z - qv.z, dw = zv.w - qv.w;
        s = m * (dx * dx + dy * dy + dz * dz + dw * dw);
        if (l == 0) {
            out_idx[row] = (float)idx;
            atomicAdd(&msum, m);
            atomicAdd(&g_n[idx], m);
        }
    }

    #pragma unroll
    for (int off = 16; off > 0; off >>= 1)
        s += __shfl_down_sync(0xffffffffu, s, off);
    int lane = tid & 31, wd = tid >> 5;
    if (lane == 0) ws[wd] = s;
    __syncthreads();
    if (tid == 0) {
        float t = 0.f;
        #pragma unroll
        for (int w = 0; w < 8; ++w) t += ws[w];
        if (t != 0.0f) atomicAdd(&g_scal[0], t * (1.0f / (float)D));
        if (msum != 0.0f) atomicAdd(&g_scal[1], msum);
    }
}

// ---------------- kernel 5: flagged-row fixup (dw into g_dw) ----------------
__global__ __launch_bounds__(256) void vq_fixup_kernel(
    const float* __restrict__ z, const float* __restrict__ cb,
    const float* __restrict__ mask,
    float* __restrict__ out_q, float* __restrict__ out_idx)
{
    __shared__ float ws[8];
    const int d = threadIdx.x;
    const int nf = g_cnt;

    for (int it = blockIdx.x; it < nf; it += gridDim.x) {
        int row = g_list[it];
        unsigned long long b = g_best[row];
        int idx = (int)(0xFFFFFFFFu - (uint32_t)(b & 0xFFFFFFFFull));
        float m  = mask[row];
        float zv = z[(size_t)row * D + d];
        float q  = cb[(size_t)idx * D + d];
        out_q[(size_t)row * D + d] = zv + (q - zv);
        atomicAdd(reinterpret_cast<float*>(g_dw4) + (size_t)idx * D + d,
                  ONE_MINUS_DECAY * m * zv);

        float diff = zv - q;
        float s = diff * diff;
        #pragma unroll
        for (int off = 16; off > 0; off >>= 1)
            s += __shfl_down_sync(0xffffffffu, s, off);
        int lane = d & 31, wd = d >> 5;
        if (lane == 0) ws[wd] = s;
        __syncthreads();
        if (d == 0) {
            float t = 0.f;
            #pragma unroll
            for (int w = 0; w < 8; ++w) t += ws[w];
            out_idx[row] = (float)idx;
            atomicAdd(&g_scal[0], m * (t * (1.0f / (float)D)));
            atomicAdd(&g_scal[1], m);
            atomicAdd(&g_n[idx], m);
        }
        __syncthreads();
    }
}

// ---------------- kernel 6: weight merge + (block 0) counts/loss finalize ----
__global__ __launch_bounds__(256) void vq_merge_final_kernel(
    const float* __restrict__ ema_weight, float* __restrict__ out_weight,
    const float* __restrict__ ema_count,
    float* __restrict__ out_count, float* __restrict__ out_loss)
{
    const int tid = threadIdx.x;
    int i = blockIdx.x * 256 + tid;   // float4 index over K*D/4
    float4 ew = reinterpret_cast<const float4*>(ema_weight)[i];
    float4 dw = g_dw4[i];
    float* o = out_weight + (size_t)i * 4;
    o[0] = EMA_DECAY * ew.x + dw.x;
    o[1] = EMA_DECAY * ew.y + dw.y;
    o[2] = EMA_DECAY * ew.z + dw.z;
    o[3] = EMA_DECAY * ew.w + dw.w;

    if (blockIdx.x != 0) return;

    // counts + loss (block 0 only)
    __shared__ float cbuf[KCODES];
    __shared__ float red[8];
    __shared__ float s_total;
    float local = 0.0f;
    for (int k = tid; k < KCODES; k += 256) {
        float c = EMA_DECAY * ema_count[k] + ONE_MINUS_DECAY * g_n[k];
        cbuf[k] = c;
        local += c;
    }
    #pragma unroll
    for (int off = 16; off > 0; off >>= 1)
        local += __shfl_down_sync(0xffffffffu, local, off);
    int lane = tid & 31, wd = tid >> 5;
    if (lane == 0) red[wd] = local;
    __syncthreads();
    if (tid == 0) {
        float v = 0.f;
        #pragma unroll
        for (int w = 0; w < 8; ++w) v += red[w];
        s_total = v;
    }
    __syncthreads();
    float total = s_total;
    float inv = total / (total + (float)KCODES * EPS);
    for (int k = tid; k < KCODES; k += 256)
        out_count[k] = (cbuf[k] + EPS) * inv;
    if (tid == 0)
        out_loss[0] = 10.0f * 0.25f * g_scal[0] / g_scal[1];
}

// ---------------- launch ----------------
extern "C" void kernel_launch(void* const* d_in, const int* in_sizes, int n_in,
                              void* d_out, int out_size)
{
    (void)in_sizes; (void)n_in; (void)out_size;
    const float* z          = (const float*)d_in[0];
    const float* mask       = (const float*)d_in[1];
    const float* cb         = (const float*)d_in[2];
    const float* ema_count  = (const float*)d_in[3];
    const float* ema_weight = (const float*)d_in[4];

    float* out        = (float*)d_out;
    float* out_q      = out;
    float* out_idx    = out_q + (size_t)NROWS * D;
    float* out_loss   = out_idx + NROWS;
    float* out_count  = out_loss + 1;
    float* out_weight = out_count + KCODES;

    static cudaStream_t s2 = nullptr;
    static cudaEvent_t evFork = nullptr, evJoin = nullptr;
    if (s2 == nullptr) {
        cudaFuncSetAttribute(vq_mma_kernel,
                             cudaFuncAttributeMaxDynamicSharedMemorySize, SMEM_TOTAL);
        cudaStreamCreateWithFlags(&s2, cudaStreamNonBlocking);
        cudaEventCreateWithFlags(&evFork, cudaEventDisableTiming);
        cudaEventCreateWithFlags(&evJoin, cudaEventDisableTiming);
    }

    vq_prep_kernel<<<P_GRID, 256>>>(z, cb);
    vq_mma_kernel<<<NROWS / BM, THREADS, SMEM_TOTAL>>>();

    // fork: rescan on s2 ∥ gather on main
    cudaEventRecord(evFork, 0);
    cudaStreamWaitEvent(s2, evFork, 0);
    vq_rescan_kernel<<<RS_GRID, 256, 0, s2>>>(z);
    cudaEventRecord(evJoin, s2);

    vq_gather_kernel<<<NROWS / 4, 256>>>(z, cb, mask, out_q, out_idx);

    cudaStreamWaitEvent(0, evJoin, 0);
    vq_fixup_kernel<<<FIXUP_GRID, 256>>>(z, cb, mask, out_q, out_idx);
    vq_merge_final_kernel<<<MERGE_GRID, 256>>>(ema_weight, out_weight,
                                               ema_count, out_count, out_loss);
}

// round 17
// speedup vs baseline: 1.0649x; 1.0649x over previous
#include <cuda_runtime.h>
#include <cuda_fp16.h>
#include <stdint.h>
#include <float.h>

// Problem constants
#define D      256
#define KCODES 4096
#define NROWS  16384

#define THREADS 512
#define BM 128
#define BN 256
#define STAGES_PER_TILE 8
#define NT (KCODES / BN)
#define TOTAL_STAGES (STAGES_PER_TILE * NT)  // 128

#define A_STAGE_BYTES (BM * 64)
#define B_STAGE_BYTES (BN * 64)
#define STAGE_BYTES   (A_STAGE_BYTES + B_STAGE_BYTES)
#define SMEM_TOTAL    (2 * STAGE_BYTES)   // 49152

#define EMA_DECAY 0.99f
#define ONE_MINUS_DECAY 0.01f
#define EPS 1e-5f
#define GAP_T 0.03f

// rescan geometry: 16 k-chunks x 256 group-slots -> one group per block (usually)
#define RG_ROWS 8
#define RS_KC   16
#define RS_GRPS 256
#define RS_GRID (RS_KC * RS_GRPS)     // 4096

// prep grid: cb jobs FIRST, then init (zero g_dw + scratch), then z pack
#define P_CB_BLOCKS   (KCODES / 32)   // 128
#define P_INIT_BLOCKS 4096            // K*D floats / 256
#define P_Z_BLOCKS    8192
#define P_GRID (P_CB_BLOCKS + P_INIT_BLOCKS + P_Z_BLOCKS)

#define FIXUP_GRID 256
#define MERGE_GRID (KCODES * D / 4 / 256)   // 1024

// ---------------- device scratch ----------------
__device__ float g_cnorm[KCODES];
__device__ float g_n[KCODES];
__device__ int   g_idx[NROWS];
__device__ int   g_flag[NROWS];
__device__ int   g_list[NROWS];
__device__ int   g_cnt;
__device__ float g_scal[2];
__device__ unsigned long long g_best[NROWS];
__device__ float g_cbT[(size_t)D * KCODES];
__device__ float4 g_dw4[(size_t)KCODES * D / 4];   // 16B-aligned dw accumulator
__device__ __half2 g_za[(size_t)NROWS * 128];
__device__ __half2 g_cbp[(size_t)KCODES * 128];

// ---------------- helpers ----------------
__device__ __forceinline__ uint32_t smem_u32(const void* p) {
    uint32_t a;
    asm("{ .reg .u64 t; cvta.to.shared.u64 t, %1; cvt.u32.u64 %0, t; }" : "=r"(a) : "l"(p));
    return a;
}
__device__ __forceinline__ void cpasync16(uint32_t dst, const void* src) {
    asm volatile("cp.async.cg.shared.global [%0], [%1], 16;" :: "r"(dst), "l"(src));
}
__device__ __forceinline__ void cp_commit() {
    asm volatile("cp.async.commit_group;" ::: "memory");
}
__device__ __forceinline__ void cp_wait1() {
    asm volatile("cp.async.wait_group 1;" ::: "memory");
}
__device__ __forceinline__ void cp_wait0() {
    asm volatile("cp.async.wait_group 0;" ::: "memory");
}
__device__ __forceinline__ void mma_f16(float* c, uint32_t a0, uint32_t a1,
                                        uint32_t a2, uint32_t a3,
                                        uint32_t b0, uint32_t b1) {
    asm volatile(
        "mma.sync.aligned.m16n8k16.row.col.f32.f16.f16.f32 "
        "{%0,%1,%2,%3}, {%4,%5,%6,%7}, {%8,%9}, {%0,%1,%2,%3};"
        : "+f"(c[0]), "+f"(c[1]), "+f"(c[2]), "+f"(c[3])
        : "r"(a0), "r"(a1), "r"(a2), "r"(a3), "r"(b0), "r"(b1));
}
__device__ __forceinline__ void red_add_v4(float* p, float a, float b, float c, float d) {
    asm volatile("red.global.add.v4.f32 [%0], {%1,%2,%3,%4};"
                 :: "l"(p), "f"(a), "f"(b), "f"(c), "f"(d) : "memory");
}
__device__ __forceinline__ unsigned long long pack_sk(float s, int k) {
    uint32_t b = __float_as_uint(s);
    b = (b & 0x80000000u) ? ~b : (b | 0x80000000u);
    return ((unsigned long long)b << 32) | (unsigned long long)(0xFFFFFFFFu - (uint32_t)k);
}
__device__ __forceinline__ int perm_d(int chunk, int ws16) {
    int p0 = ws16 * 2;
    int q = p0 >> 3, j = p0 & 7;
    int kl = 2 * q + ((j >> 1) << 3) + (j & 1);
    return chunk * 32 + kl;
}

// ---------------- kernel 1: fused prep ----------------
__global__ __launch_bounds__(256) void vq_prep_kernel(
    const float* __restrict__ z, const float* __restrict__ cb)
{
    const int b = blockIdx.x;
    const int tid = threadIdx.x;

    if (b < P_CB_BLOCKS) {
        __shared__ float s[32][257];
        const int k0 = b * 32;
        for (int i = tid; i < 32 * 256; i += 256)
            s[i >> 8][i & 255] = cb[(size_t)(k0 + (i >> 8)) * D + (i & 255)];
        __syncthreads();

        const int wid = tid >> 5, lane = tid & 31;
        #pragma unroll
        for (int rr = 0; rr < 4; ++rr) {
            int r = wid * 4 + rr;
            float sum = 0.f;
            #pragma unroll
            for (int j = 0; j < 8; ++j) { float v = s[r][lane + 32 * j]; sum += v * v; }
            #pragma unroll
            for (int off = 16; off > 0; off >>= 1)
                sum += __shfl_down_sync(0xffffffffu, sum, off);
            if (lane == 0) g_cnorm[k0 + r] = 0.5f * sum;
        }
        for (int i = tid; i < 32 * 256; i += 256) {
            int d = i >> 5, j = i & 31;
            g_cbT[(size_t)d * KCODES + k0 + j] = s[j][d];
        }
        for (int i = tid; i < 32 * 128; i += 256) {
            int row = i >> 7, wi = i & 127;
            int d = perm_d(wi >> 4, wi & 15);
            g_cbp[(size_t)(k0 + row) * 128 + wi] =
                __halves2half2(__float2half_rn(s[row][d]), __float2half_rn(s[row][d + 1]));
        }
        return;
    }
    if (b < P_CB_BLOCKS + P_INIT_BLOCKS) {
        int i = (b - P_CB_BLOCKS) * 256 + tid;     // covers K*D floats
        reinterpret_cast<float*>(g_dw4)[i] = 0.0f;
        if (i < KCODES) g_n[i] = 0.0f;
        if (i < NROWS) g_best[i] = 0ull;
        if (i < 2) g_scal[i] = 0.0f;
        if (i == 0) g_cnt = 0;
        return;
    }
    {
        int w   = (b - P_CB_BLOCKS - P_INIT_BLOCKS) * 256 + tid;
        int row = w >> 7;
        int wi  = w & 127;
        int d   = perm_d(wi >> 4, wi & 15);
        float x0 = z[(size_t)row * D + d];
        float x1 = z[(size_t)row * D + d + 1];
        g_za[w] = __halves2half2(__float2half_rn(x0), __float2half_rn(x1));
    }
}

// ---------------- kernel 2: fp16 1-term GEMM + top-2 argmax + compact ----------
__global__ __launch_bounds__(THREADS, 1) void vq_mma_kernel()
{
    extern __shared__ char smem[];
    const uint32_t sbase = smem_u32(smem);
    const int tid  = threadIdx.x;
    const int wid  = tid >> 5;
    const int lane = tid & 31;
    const int r    = lane >> 2;
    const int q    = lane & 3;
    const int wm   = (wid >> 2) * 32;
    const int wn   = (wid & 3) * 64;
    const int mBase = blockIdx.x * BM;

    uint32_t aoff[2][2];
    #pragma unroll
    for (int mf = 0; mf < 2; ++mf)
        #pragma unroll
        for (int rr = 0; rr < 2; ++rr)
            aoff[mf][rr] = (uint32_t)(wm + mf * 16 + rr * 8 + r) * 64u + (uint32_t)q * 16u;
    uint32_t boff[8];
    #pragma unroll
    for (int nf = 0; nf < 8; ++nf)
        boff[nf] = (uint32_t)(wn + nf * 8 + r) * 64u + (uint32_t)q * 16u;

    float acc[2][8][4];
    float bestS[2][2], secS[2][2];
    int   bestI[2][2];
    #pragma unroll
    for (int mf = 0; mf < 2; ++mf)
        #pragma unroll
        for (int rr = 0; rr < 2; ++rr) {
            bestS[mf][rr] = -FLT_MAX; secS[mf][rr] = -FLT_MAX; bestI[mf][rr] = 0x7fffffff;
        }

    auto issue = [&](int s, int buf) {
        int nt = s >> 3;
        int kc = s & 7;
        const __half2* Asrc = g_za  + (size_t)mBase * 128 + kc * 16;
        const __half2* Bsrc = g_cbp + (size_t)(nt * BN) * 128 + kc * 16;
        uint32_t abase = sbase + (uint32_t)buf * STAGE_BYTES;
        uint32_t bbase = abase + A_STAGE_BYTES;
        {
            int i = tid;
            int row = i >> 2, c = i & 3;
            cpasync16(abase + (uint32_t)row * 64u + (uint32_t)c * 16u,
                      Asrc + (size_t)row * 128 + c * 4);
        }
        #pragma unroll
        for (int t = 0; t < 2; ++t) {
            int i = tid + t * THREADS;
            int row = i >> 2, c = i & 3;
            cpasync16(bbase + (uint32_t)row * 64u + (uint32_t)c * 16u,
                      Bsrc + (size_t)row * 128 + c * 4);
        }
        cp_commit();
    };

    issue(0, 0);

    for (int s = 0; s < TOTAL_STAGES; ++s) {
        const int buf = s & 1;
        if (s < TOTAL_STAGES - 1) { issue(s + 1, buf ^ 1); cp_wait1(); }
        else                       { cp_wait0(); }
        __syncthreads();

        int nt = s >> 3;
        int ks = s & 7;
        if (ks == 0) {
            #pragma unroll
            for (int mf = 0; mf < 2; ++mf)
                #pragma unroll
                for (int nf = 0; nf < 8; ++nf)
                    #pragma unroll
                    for (int e = 0; e < 4; ++e) acc[mf][nf][e] = 0.0f;
        }

        uint32_t abase = sbase + (uint32_t)buf * STAGE_BYTES;
        uint32_t bbase = abase + A_STAGE_BYTES;

        uint4 Af[2][2];
        #pragma unroll
        for (int mf = 0; mf < 2; ++mf)
            #pragma unroll
            for (int rr = 0; rr < 2; ++rr) {
                uint32_t addr = abase + aoff[mf][rr];
                asm volatile("ld.shared.v4.b32 {%0,%1,%2,%3}, [%4];"
                    : "=r"(Af[mf][rr].x), "=r"(Af[mf][rr].y),
                      "=r"(Af[mf][rr].z), "=r"(Af[mf][rr].w)
                    : "r"(addr));
            }
        #pragma unroll
        for (int nf = 0; nf < 8; ++nf) {
            uint4 Bf;
            uint32_t addr = bbase + boff[nf];
            asm volatile("ld.shared.v4.b32 {%0,%1,%2,%3}, [%4];"
                : "=r"(Bf.x), "=r"(Bf.y), "=r"(Bf.z), "=r"(Bf.w)
                : "r"(addr));
            #pragma unroll
            for (int mf = 0; mf < 2; ++mf) {
                mma_f16(acc[mf][nf],
                        Af[mf][0].x, Af[mf][1].x, Af[mf][0].y, Af[mf][1].y,
                        Bf.x, Bf.y);
                mma_f16(acc[mf][nf],
                        Af[mf][0].z, Af[mf][1].z, Af[mf][0].w, Af[mf][1].w,
                        Bf.z, Bf.w);
            }
        }

        if (ks == STAGES_PER_TILE - 1) {
            int ntBase = nt * BN;
            #pragma unroll
            for (int nf = 0; nf < 8; ++nf) {
                int colb = ntBase + wn + nf * 8 + q * 2;
                float cn0 = __ldg(&g_cnorm[colb]);
                float cn1 = __ldg(&g_cnorm[colb + 1]);
                #pragma unroll
                for (int mf = 0; mf < 2; ++mf) {
                    float sc[4];
                    sc[0] = acc[mf][nf][0] - cn0;
                    sc[1] = acc[mf][nf][1] - cn1;
                    sc[2] = acc[mf][nf][2] - cn0;
                    sc[3] = acc[mf][nf][3] - cn1;
                    #pragma unroll
                    for (int e = 0; e < 4; ++e) {
                        int rr = e >> 1;
                        int kk = colb + (e & 1);
                        float v = sc[e];
                        if (v > bestS[mf][rr]) {
                            secS[mf][rr] = bestS[mf][rr];
                            bestS[mf][rr] = v; bestI[mf][rr] = kk;
                        } else if (v > secS[mf][rr]) {
                            secS[mf][rr] = v;
                        }
                    }
                }
            }
        }
        __syncthreads();
    }

    float* redS  = reinterpret_cast<float*>(smem);
    int*   redI  = reinterpret_cast<int*>(smem + BM * 16 * 4);
    float* redS2 = reinterpret_cast<float*>(smem + BM * 16 * 8);
    int c16 = (wid & 3) * 4 + q;
    #pragma unroll
    for (int mf = 0; mf < 2; ++mf)
        #pragma unroll
        for (int rr = 0; rr < 2; ++rr) {
            int row = wm + mf * 16 + rr * 8 + r;
            redS [row * 16 + c16] = bestS[mf][rr];
            redI [row * 16 + c16] = bestI[mf][rr];
            redS2[row * 16 + c16] = secS[mf][rr];
        }
    __syncthreads();
    if (tid < BM) {
        float bs = redS[tid * 16];
        int   bi = redI[tid * 16];
        float ss = redS2[tid * 16];
        #pragma unroll
        for (int j = 1; j < 16; ++j) {
            float sv  = redS [tid * 16 + j];
            int   iv  = redI [tid * 16 + j];
            float s2v = redS2[tid * 16 + j];
            if (sv > bs || (sv == bs && iv < bi)) {
                ss = fmaxf(bs, s2v);
                bs = sv; bi = iv;
            } else {
                ss = fmaxf(ss, sv);
            }
        }
        int row = mBase + tid;
        int flag = (bs - ss < GAP_T) ? 1 : 0;
        g_idx[row]  = bi;
        g_flag[row] = flag;
        if (flag) {
            int p = atomicAdd(&g_cnt, 1);
            g_list[p] = row;
        }
    }
}

// ---------------- kernel 3 (s2): batched exact fp32 rescan ----------------
// 16 k-chunks x 256 group-slots; with nf <= 2048 each block runs ONE group
__global__ __launch_bounds__(256) void vq_rescan_kernel(const float* __restrict__ z)
{
    __shared__ float zs[RG_ROWS][256];
    __shared__ int   rows[RG_ROWS];
    __shared__ unsigned long long wbuf[RG_ROWS][8];

    const int tid  = threadIdx.x;
    const int lane = tid & 31;
    const int wid  = tid >> 5;
    const int k0   = (blockIdx.x & (RS_KC - 1)) * 256 + tid;
    const int nf   = g_cnt;
    const int ngrp = (nf + RG_ROWS - 1) / RG_ROWS;

    const float cn = g_cnorm[k0];

    for (int grp = blockIdx.x >> 4; grp < ngrp; grp += RS_GRPS) {
        __syncthreads();
        if (tid < RG_ROWS) {
            int i = grp * RG_ROWS + tid;
            rows[tid] = (i < nf) ? g_list[i] : -1;
        }
        __syncthreads();
        #pragma unroll
        for (int rr = 0; rr < RG_ROWS; ++rr) {
            int row = rows[rr];
            if (row >= 0) zs[rr][tid] = z[(size_t)row * D + tid];
        }
        __syncthreads();

        float acc[RG_ROWS];
        #pragma unroll
        for (int rr = 0; rr < RG_ROWS; ++rr) acc[rr] = 0.f;

        #pragma unroll 4
        for (int d4 = 0; d4 < D; d4 += 4) {
            float4 c;
            const float* p = g_cbT + (size_t)d4 * KCODES + k0;
            c.x = p[0];
            c.y = p[KCODES];
            c.z = p[2 * KCODES];
            c.w = p[3 * KCODES];
            #pragma unroll
            for (int rr = 0; rr < RG_ROWS; ++rr) {
                float4 zv = *reinterpret_cast<const float4*>(&zs[rr][d4]);
                acc[rr] += c.x * zv.x + c.y * zv.y + c.z * zv.z + c.w * zv.w;
            }
        }

        #pragma unroll
        for (int rr = 0; rr < RG_ROWS; ++rr) {
            unsigned long long pm = pack_sk(acc[rr] - cn, k0);
            #pragma unroll
            for (int off = 16; off > 0; off >>= 1) {
                unsigned long long qv = __shfl_xor_sync(0xffffffffu, pm, off);
                if (qv > pm) pm = qv;
            }
            if (lane == 0) wbuf[rr][wid] = pm;
        }
        __syncthreads();
        if (tid < RG_ROWS && rows[tid] >= 0) {
            unsigned long long pm = wbuf[tid][0];
            #pragma unroll
            for (int w = 1; w < 8; ++w)
                if (wbuf[tid][w] > pm) pm = wbuf[tid][w];
            atomicMax(&g_best[rows[tid]], pm);
        }
    }
}

// ---------------- kernel 4: gather for UNFLAGGED rows (v4 red into g_dw) -----
__global__ __launch_bounds__(256) void vq_gather_kernel(
    const float* __restrict__ z, const float* __restrict__ cb,
    const float* __restrict__ mask,
    float* __restrict__ out_q, float* __restrict__ out_idx)
{
    __shared__ float ws[8];
    __shared__ float msum;
    int tid = threadIdx.x;
    int l   = tid & 63;
    int row = blockIdx.x * 4 + (tid >> 6);
    int flag = g_flag[row];
    if (tid == 0) msum = 0.0f;
    __syncthreads();

    float s = 0.0f;
    if (!flag) {
        int idx = g_idx[row];
        float m = mask[row];
        float4 zv = reinterpret_cast<const float4*>(z  + (size_t)row * D)[l];
        float4 qv = reinterpret_cast<const float4*>(cb + (size_t)idx * D)[l];
        float4 o;
        o.x = zv.x + (qv.x - zv.x); o.y = zv.y + (qv.y - zv.y);
        o.z = zv.z + (qv.z - zv.z); o.w = zv.w + (qv.w - zv.w);
        reinterpret_cast<float4*>(out_q + (size_t)row * D)[l] = o;

        if (m != 0.0f) {
            red_add_v4(reinterpret_cast<float*>(g_dw4) + (size_t)idx * D + l * 4,
                       ONE_MINUS_DECAY * m * zv.x, ONE_MINUS_DECAY * m * zv.y,
                       ONE_MINUS_DECAY * m * zv.z, ONE_MINUS_DECAY * m * zv.w);
        }
        float dx = zv.x - qv.x, dy = zv.y - qv.y, dz = zv.z - qv.z, dw = zv.w - qv.w;
        s = m * (dx * dx + dy * dy + dz * dz + dw * dw);
        if (l == 0) {
            out_idx[row] = (float)idx;
            atomicAdd(&msum, m);
            atomicAdd(&g_n[idx], m);
        }
    }

    #pragma unroll
    for (int off = 16; off > 0; off >>= 1)
        s += __shfl_down_sync(0xffffffffu, s, off);
    int lane = tid & 31, wd = tid >> 5;
    if (lane == 0) ws[wd] = s;
    __syncthreads();
    if (tid == 0) {
        float t = 0.f;
        #pragma unroll
        for (int w = 0; w < 8; ++w) t += ws[w];
        if (t != 0.0f) atomicAdd(&g_scal[0], t * (1.0f / (float)D));
        if (msum != 0.0f) atomicAdd(&g_scal[1], msum);
    }
}

// ---------------- kernel 5: flagged-row fixup (dw into g_dw) ----------------
__global__ __launch_bounds__(256) void vq_fixup_kernel(
    const float* __restrict__ z, const float* __restrict__ cb,
    const float* __restrict__ mask,
    float* __restrict__ out_q, float* __restrict__ out_idx)
{
    __shared__ float ws[8];
    const int d = threadIdx.x;
    const int nf = g_cnt;

    for (int it = blockIdx.x; it < nf; it += gridDim.x) {
        int row = g_list[it];
        unsigned long long b = g_best[row];
        int idx = (int)(0xFFFFFFFFu - (uint32_t)(b & 0xFFFFFFFFull));
        float m  = mask[row];
        float zv = z[(size_t)row * D + d];
        float q  = cb[(size_t)idx * D + d];
        out_q[(size_t)row * D + d] = zv + (q - zv);
        atomicAdd(reinterpret_cast<float*>(g_dw4) + (size_t)idx * D + d,
                  ONE_MINUS_DECAY * m * zv);

        float diff = zv - q;
        float s = diff * diff;
        #pragma unroll
        for (int off = 16; off > 0; off >>= 1)
            s += __shfl_down_sync(0xffffffffu, s, off);
        int lane = d & 31, wd = d >> 5;
        if (lane == 0) ws[wd] = s;
        __syncthreads();
        if (d == 0) {
            float t = 0.f;
            #pragma unroll
            for (int w = 0; w < 8; ++w) t += ws[w];
            out_idx[row] = (float)idx;
            atomicAdd(&g_scal[0], m * (t * (1.0f / (float)D)));
            atomicAdd(&g_scal[1], m);
            atomicAdd(&g_n[idx], m);
        }
        __syncthreads();
    }
}

// ---------------- kernel 6: weight merge + (block 0) counts/loss finalize ----
__global__ __launch_bounds__(256) void vq_merge_final_kernel(
    const float* __restrict__ ema_weight, float* __restrict__ out_weight,
    const float* __restrict__ ema_count,
    float* __restrict__ out_count, float* __restrict__ out_loss)
{
    const int tid = threadIdx.x;
    int i = blockIdx.x * 256 + tid;   // float4 index over K*D/4
    float4 ew = reinterpret_cast<const float4*>(ema_weight)[i];
    float4 dw = g_dw4[i];
    float* o = out_weight + (size_t)i * 4;
    o[0] = EMA_DECAY * ew.x + dw.x;
    o[1] = EMA_DECAY * ew.y + dw.y;
    o[2] = EMA_DECAY * ew.z + dw.z;
    o[3] = EMA_DECAY * ew.w + dw.w;

    if (blockIdx.x != 0) return;

    // counts + loss (block 0 only)
    __shared__ float cbuf[KCODES];
    __shared__ float red[8];
    __shared__ float s_total;
    float local = 0.0f;
    for (int k = tid; k < KCODES; k += 256) {
        float c = EMA_DECAY * ema_count[k] + ONE_MINUS_DECAY * g_n[k];
        cbuf[k] = c;
        local += c;
    }
    #pragma unroll
    for (int off = 16; off > 0; off >>= 1)
        local += __shfl_down_sync(0xffffffffu, local, off);
    int lane = tid & 31, wd = tid >> 5;
    if (lane == 0) red[wd] = local;
    __syncthreads();
    if (tid == 0) {
        float v = 0.f;
        #pragma unroll
        for (int w = 0; w < 8; ++w) v += red[w];
        s_total = v;
    }
    __syncthreads();
    float total = s_total;
    float inv = total / (total + (float)KCODES * EPS);
    for (int k = tid; k < KCODES; k += 256)
        out_count[k] = (cbuf[k] + EPS) * inv;
    if (tid == 0)
        out_loss[0] = 10.0f * 0.25f * g_scal[0] / g_scal[1];
}

// ---------------- launch ----------------
extern "C" void kernel_launch(void* const* d_in, const int* in_sizes, int n_in,
                              void* d_out, int out_size)
{
    (void)in_sizes; (void)n_in; (void)out_size;
    const float* z          = (const float*)d_in[0];
    const float* mask       = (const float*)d_in[1];
    const float* cb         = (const float*)d_in[2];
    const float* ema_count  = (const float*)d_in[3];
    const float* ema_weight = (const float*)d_in[4];

    float* out        = (float*)d_out;
    float* out_q      = out;
    float* out_idx    = out_q + (size_t)NROWS * D;
    float* out_loss   = out_idx + NROWS;
    float* out_count  = out_loss + 1;
    float* out_weight = out_count + KCODES;

    static cudaStream_t s2 = nullptr;
    static cudaEvent_t evFork = nullptr, evJoin = nullptr;
    if (s2 == nullptr) {
        cudaFuncSetAttribute(vq_mma_kernel,
                             cudaFuncAttributeMaxDynamicSharedMemorySize, SMEM_TOTAL);
        cudaStreamCreateWithFlags(&s2, cudaStreamNonBlocking);
        cudaEventCreateWithFlags(&evFork, cudaEventDisableTiming);
        cudaEventCreateWithFlags(&evJoin, cudaEventDisableTiming);
    }

    vq_prep_kernel<<<P_GRID, 256>>>(z, cb);
    vq_mma_kernel<<<NROWS / BM, THREADS, SMEM_TOTAL>>>();

    // fork: rescan on s2 ∥ gather on main
    cudaEventRecord(evFork, 0);
    cudaStreamWaitEvent(s2, evFork, 0);
    vq_rescan_kernel<<<RS_GRID, 256, 0, s2>>>(z);
    cudaEventRecord(evJoin, s2);

    vq_gather_kernel<<<NROWS / 4, 256>>>(z, cb, mask, out_q, out_idx);

    cudaStreamWaitEvent(0, evJoin, 0);
    vq_fixup_kernel<<<FIXUP_GRID, 256>>>(z, cb, mask, out_q, out_idx);
    vq_merge_final_kernel<<<MERGE_GRID, 256>>>(ema_weight, out_weight,
                                               ema_count, out_count, out_loss);
}